// round 1
// baseline (speedup 1.0000x reference)
#include <cuda_runtime.h>
#include <math.h>
#include <stdint.h>

// Problem constants (RnnSenderGS): B=4096, D_IN=512, H=512, E=256, V=512, L=32
#define Bb   4096
#define DIN  512
#define Hh   512
#define Ee   256
#define Vv   512
#define Ll   32
#define MIN_REAL_F (-3.4028234663852886e+38f)

// Persistent state / scratch (no allocations allowed)
__device__ float g_h[Bb * Hh];          // hidden state       [B,H]
__device__ float g_e[Bb * Ee];          // embedding input    [B,E]
__device__ float g_gi[Bb * 3 * Hh];     // input gates        [B,3H]
__device__ float g_gh[Bb * 3 * Hh];     // hidden gates       [B,3H]
__device__ float g_logits[Bb * Vv];     // logits             [B,V]

// ---------------------------------------------------------------------------
// C[M,N] = A[M,K] @ W[N,K]^T + bias[N]
// A row stride = lda, W row stride = K (contiguous), C row stride = ldc.
// Tile: BM=128, BN=128, BK=8, per-thread 8x8, 256 threads.
// All dims in this problem are divisible by the tile sizes -> no bounds checks.
// ---------------------------------------------------------------------------
__global__ __launch_bounds__(256) void sgemm_nt(
    const float* __restrict__ A, const float* __restrict__ W,
    const float* __restrict__ bias, float* __restrict__ C,
    int K, int lda, int ldc)
{
    constexpr int BM = 128, BN = 128, BK = 8, TM = 8, TN = 8;
    __shared__ float As[BK][BM];
    __shared__ float Ws[BK][BN];

    const int tid = threadIdx.x;
    const int bm = blockIdx.y * BM;
    const int bn = blockIdx.x * BN;
    const int tx = tid % (BN / TN);   // 0..15
    const int ty = tid / (BN / TN);   // 0..15

    // Loads: 128 rows x 8 cols = 256 float4 per tile, one per thread.
    const int ldRow = tid >> 1;          // 0..127
    const int ldCol = (tid & 1) * 4;     // 0 or 4
    const float* Aptr = A + (size_t)(bm + ldRow) * lda + ldCol;
    const float* Wptr = W + (size_t)(bn + ldRow) * K + ldCol;

    float acc[TM][TN];
#pragma unroll
    for (int i = 0; i < TM; i++)
#pragma unroll
        for (int j = 0; j < TN; j++) acc[i][j] = 0.0f;

    for (int k0 = 0; k0 < K; k0 += BK) {
        float4 av = *(const float4*)(Aptr + k0);
        float4 wv = *(const float4*)(Wptr + k0);
        As[ldCol + 0][ldRow] = av.x;
        As[ldCol + 1][ldRow] = av.y;
        As[ldCol + 2][ldRow] = av.z;
        As[ldCol + 3][ldRow] = av.w;
        Ws[ldCol + 0][ldRow] = wv.x;
        Ws[ldCol + 1][ldRow] = wv.y;
        Ws[ldCol + 2][ldRow] = wv.z;
        Ws[ldCol + 3][ldRow] = wv.w;
        __syncthreads();

#pragma unroll
        for (int k = 0; k < BK; k++) {
            float a[TM], w[TN];
#pragma unroll
            for (int i = 0; i < TM; i++) a[i] = As[k][ty * TM + i];
#pragma unroll
            for (int j = 0; j < TN; j++) w[j] = Ws[k][tx * TN + j];
#pragma unroll
            for (int i = 0; i < TM; i++)
#pragma unroll
                for (int j = 0; j < TN; j++) acc[i][j] += a[i] * w[j];
        }
        __syncthreads();
    }

    float bv[TN];
#pragma unroll
    for (int j = 0; j < TN; j++) bv[j] = bias[bn + tx * TN + j];

#pragma unroll
    for (int i = 0; i < TM; i++) {
        float* crow = C + (size_t)(bm + ty * TM + i) * ldc + bn + tx * TN;
        float4 o0, o1;
        o0.x = acc[i][0] + bv[0]; o0.y = acc[i][1] + bv[1];
        o0.z = acc[i][2] + bv[2]; o0.w = acc[i][3] + bv[3];
        o1.x = acc[i][4] + bv[4]; o1.y = acc[i][5] + bv[5];
        o1.z = acc[i][6] + bv[6]; o1.w = acc[i][7] + bv[7];
        *(float4*)(crow)     = o0;
        *(float4*)(crow + 4) = o1;
    }
}

// ---------------------------------------------------------------------------
// e0[b,:] = sos_embedding
// ---------------------------------------------------------------------------
__global__ void init_e_kernel(float* __restrict__ e, const float* __restrict__ sos)
{
    int idx = blockIdx.x * blockDim.x + threadIdx.x;
    if (idx < Bb * Ee) e[idx] = sos[idx & (Ee - 1)];
}

// ---------------------------------------------------------------------------
// GRU gate fusion (torch GRUCell semantics):
//   r = sigmoid(gi_r + gh_r); z = sigmoid(gi_z + gh_z)
//   n = tanh(gi_n + r * gh_n); h = (1-z)*n + z*h
// ---------------------------------------------------------------------------
__global__ void gru_gates_kernel(const float* __restrict__ gi,
                                 const float* __restrict__ gh,
                                 float* __restrict__ h)
{
    int idx = blockIdx.x * blockDim.x + threadIdx.x;
    if (idx >= Bb * Hh) return;
    int b = idx / Hh;
    int j = idx - b * Hh;
    const float* gib = gi + (size_t)b * 3 * Hh;
    const float* ghb = gh + (size_t)b * 3 * Hh;
    float r = 1.0f / (1.0f + expf(-(gib[j] + ghb[j])));
    float z = 1.0f / (1.0f + expf(-(gib[Hh + j] + ghb[Hh + j])));
    float n = tanhf(gib[2 * Hh + j] + r * ghb[2 * Hh + j]);
    h[idx] = (1.0f - z) * n + z * h[idx];
}

// ---------------------------------------------------------------------------
// Gumbel-softmax + entropy, one block (512 threads) per batch row.
//   t = logits + (-log(-log(u)))  (TEMP = 1)
//   sample = softmax(t); entropy = -sum p * max(log2 p, MIN_REAL)
// seq row stride = L*V (written into the final [B,L,V] layout), ent stride L.
// ---------------------------------------------------------------------------
__global__ __launch_bounds__(512) void gumbel_softmax_kernel(
    const float* __restrict__ logits,
    const float* __restrict__ noise,     // [B,V] slab for this step
    float* __restrict__ seq,             // out + l*V  (row stride L*V)
    float* __restrict__ ent)             // out + B*L*V + l (row stride L)
{
    __shared__ float sm[16];
    __shared__ float bc;
    const int b = blockIdx.x;
    const int tid = threadIdx.x;

    float u = noise[(size_t)b * Vv + tid];
    float t = logits[(size_t)b * Vv + tid] - logf(-logf(u));

    // --- max reduction ---
    float v = t;
#pragma unroll
    for (int o = 16; o; o >>= 1) v = fmaxf(v, __shfl_xor_sync(0xffffffffu, v, o));
    if ((tid & 31) == 0) sm[tid >> 5] = v;
    __syncthreads();
    if (tid < 32) {
        float w = sm[tid & 15];
#pragma unroll
        for (int o = 16; o; o >>= 1) w = fmaxf(w, __shfl_xor_sync(0xffffffffu, w, o));
        if (tid == 0) bc = w;
    }
    __syncthreads();
    const float tmax = bc;
    __syncthreads();

    // --- sum of exp ---
    float ex = expf(t - tmax);
    v = ex;
#pragma unroll
    for (int o = 16; o; o >>= 1) v += __shfl_xor_sync(0xffffffffu, v, o);
    if ((tid & 31) == 0) sm[tid >> 5] = v;
    __syncthreads();
    if (tid < 32) {
        float w = (tid < 16) ? sm[tid] : 0.0f;
#pragma unroll
        for (int o = 16; o; o >>= 1) w += __shfl_xor_sync(0xffffffffu, w, o);
        if (tid == 0) bc = w;
    }
    __syncthreads();
    const float inv = 1.0f / bc;
    __syncthreads();

    const float p = ex * inv;
    seq[(size_t)b * (Ll * Vv) + tid] = p;

    // --- entropy: -sum p * max(log2(p), MIN_REAL)  (p==0 contributes 0) ---
    float el = p * fmaxf(log2f(p), MIN_REAL_F);
    v = el;
#pragma unroll
    for (int o = 16; o; o >>= 1) v += __shfl_xor_sync(0xffffffffu, v, o);
    if ((tid & 31) == 0) sm[tid >> 5] = v;
    __syncthreads();
    if (tid < 32) {
        float w = (tid < 16) ? sm[tid] : 0.0f;
#pragma unroll
        for (int o = 16; o; o >>= 1) w += __shfl_xor_sync(0xffffffffu, w, o);
        if (tid == 0) ent[(size_t)b * Ll] = -w;
    }
}

// ---------------------------------------------------------------------------
// Host launcher: h0 GEMM, e0 init, then 32 steps of
//   gi GEMM -> gh GEMM -> gates -> logits GEMM -> gumbel softmax -> emb GEMM
// All launches on the default stream (graph-capturable, no allocations).
// ---------------------------------------------------------------------------
extern "C" void kernel_launch(void* const* d_in, const int* in_sizes, int n_in,
                              void* d_out, int out_size)
{
    const float* x       = (const float*)d_in[0];
    const float* noise   = (const float*)d_in[1];  // [L,B,V]
    const float* W_agent = (const float*)d_in[2];  // [H,DIN]
    const float* b_agent = (const float*)d_in[3];
    const float* W_ih    = (const float*)d_in[4];  // [3H,E]
    const float* W_hh    = (const float*)d_in[5];  // [3H,H]
    const float* b_ih    = (const float*)d_in[6];
    const float* b_hh    = (const float*)d_in[7];
    const float* W_out   = (const float*)d_in[8];  // [V,H]
    const float* b_out   = (const float*)d_in[9];
    const float* W_emb   = (const float*)d_in[10]; // [E,V]
    const float* b_emb   = (const float*)d_in[11];
    const float* sos     = (const float*)d_in[12]; // [E]

    float* out = (float*)d_out;
    float* seq = out;                              // [B,L,V]
    float* ent = out + (size_t)Bb * Ll * Vv;       // [B,L]

    float *h, *e, *gi, *gh, *logits;
    cudaGetSymbolAddress((void**)&h,      g_h);
    cudaGetSymbolAddress((void**)&e,      g_e);
    cudaGetSymbolAddress((void**)&gi,     g_gi);
    cudaGetSymbolAddress((void**)&gh,     g_gh);
    cudaGetSymbolAddress((void**)&logits, g_logits);

    const dim3 blk(256);
    const dim3 gM = dim3(0, Bb / 128);  // y fixed; x per-call

    // h0 = x @ W_agent^T + b_agent   (M=4096, N=512, K=512)
    sgemm_nt<<<dim3(Hh / 128, Bb / 128), blk>>>(x, W_agent, b_agent, h, DIN, DIN, Hh);
    // e0 = broadcast(sos)
    init_e_kernel<<<(Bb * Ee + 255) / 256, 256>>>(e, sos);

    for (int l = 0; l < Ll; l++) {
        // gi = e @ W_ih^T + b_ih   (N=1536, K=256)
        sgemm_nt<<<dim3(3 * Hh / 128, Bb / 128), blk>>>(e, W_ih, b_ih, gi, Ee, Ee, 3 * Hh);
        // gh = h @ W_hh^T + b_hh   (N=1536, K=512)
        sgemm_nt<<<dim3(3 * Hh / 128, Bb / 128), blk>>>(h, W_hh, b_hh, gh, Hh, Hh, 3 * Hh);
        // h = GRU(gi, gh, h)
        gru_gates_kernel<<<(Bb * Hh + 255) / 256, 256>>>(gi, gh, h);
        // logits = h @ W_out^T + b_out   (N=512, K=512)
        sgemm_nt<<<dim3(Vv / 128, Bb / 128), blk>>>(h, W_out, b_out, logits, Hh, Hh, Vv);
        // sample + entropy (writes sample straight into d_out's [B,L,V] layout)
        gumbel_softmax_kernel<<<Bb, 512>>>(logits,
                                           noise + (size_t)l * Bb * Vv,
                                           seq + (size_t)l * Vv,
                                           ent + l);
        // e = sample @ W_emb^T + b_emb   (N=256, K=512, A = seq slab, lda = L*V)
        sgemm_nt<<<dim3(Ee / 128, Bb / 128), blk>>>(seq + (size_t)l * Vv, W_emb, b_emb, e,
                                                    Vv, Ll * Vv, Ee);
    }
    (void)in_sizes; (void)n_in; (void)out_size; (void)gM;
}

// round 2
// speedup vs baseline: 2.9408x; 2.9408x over previous
#include <cuda_runtime.h>
#include <math.h>
#include <stdint.h>

// Problem constants: B=4096, D_IN=512, H=512, E=256, V=512, L=32
#define Bb   4096
#define DIN  512
#define Hh   512
#define Ee   256
#define Vv   512
#define Ll   32
#define MIN_REAL_F (-3.4028234663852886e+38f)

// Persistent state / scratch (no allocations allowed)
__device__ float g_h[Bb * Hh];
__device__ float g_e[Bb * Ee];
__device__ float g_gi[Bb * 3 * Hh];
__device__ float g_gh[Bb * 3 * Hh];
__device__ float g_logits[Bb * Vv];

// ---------------------------------------------------------------------------
// PTX helpers
// ---------------------------------------------------------------------------
__device__ __forceinline__ uint32_t smem_u32(const void* p) {
    return (uint32_t)__cvta_generic_to_shared(p);
}
__device__ __forceinline__ void cp16(uint32_t s, const void* g) {
    asm volatile("cp.async.cg.shared.global [%0], [%1], 16;\n" :: "r"(s), "l"(g));
}
__device__ __forceinline__ void cp_commit() {
    asm volatile("cp.async.commit_group;\n");
}
template<int N> __device__ __forceinline__ void cp_wait() {
    asm volatile("cp.async.wait_group %0;\n" :: "n"(N));
}
__device__ __forceinline__ uint32_t f2tf32(float f) {
    uint32_t r; asm("cvt.rna.tf32.f32 %0, %1;\n" : "=r"(r) : "f"(f)); return r;
}
__device__ __forceinline__ void mma_tf32(float c[4],
    uint32_t a0, uint32_t a1, uint32_t a2, uint32_t a3,
    uint32_t b0, uint32_t b1)
{
    asm volatile(
        "mma.sync.aligned.m16n8k8.row.col.f32.tf32.tf32.f32 "
        "{%0,%1,%2,%3}, {%4,%5,%6,%7}, {%8,%9}, {%0,%1,%2,%3};\n"
        : "+f"(c[0]), "+f"(c[1]), "+f"(c[2]), "+f"(c[3])
        : "r"(a0), "r"(a1), "r"(a2), "r"(a3), "r"(b0), "r"(b1));
}

// ---------------------------------------------------------------------------
// TF32 tensor-core GEMM:  C[M,N] = A[M,K] @ W[N,K]^T + bias[N]
// BM=128, BN=128, BK=16; 256 threads = 8 warps (2 x 4), warp tile 64x32.
// 2-stage cp.async double buffering. All dims divisible by tiles (checked).
// ---------------------------------------------------------------------------
#define BMt 128
#define BNt 128
#define BKt 16
#define PADt 20   // floats per smem row (16 data + 4 pad): 80B, 16B-aligned, conflict-free

__global__ __launch_bounds__(256, 2) void tgemm_nt(
    const float* __restrict__ A, const float* __restrict__ W,
    const float* __restrict__ bias, float* __restrict__ C,
    int K, int lda, int ldc)
{
    __shared__ float As[2][BMt * PADt];
    __shared__ float Ws[2][BNt * PADt];

    const int tid  = threadIdx.x;
    const int warp = tid >> 5;
    const int lane = tid & 31;
    const int wm = (warp & 1) * 64;     // warp row offset in tile
    const int wn = (warp >> 1) * 32;    // warp col offset in tile
    const int g  = lane >> 2;           // 0..7
    const int t  = lane & 3;            // 0..3
    const int bm = blockIdx.y * BMt;
    const int bn = blockIdx.x * BNt;

    // global->smem copy mapping: thread copies 2x16B of A and 2x16B of W
    const int crow = tid >> 1;          // 0..127
    const int ccol = (tid & 1) * 8;     // 0 or 8 (floats)
    const float* Ag = A + (size_t)(bm + crow) * lda + ccol;
    const float* Wg = W + (size_t)(bn + crow) * K + ccol;

    uint32_t aB[2], wB[2];
    aB[0] = smem_u32(&As[0][crow * PADt + ccol]);
    aB[1] = smem_u32(&As[1][crow * PADt + ccol]);
    wB[0] = smem_u32(&Ws[0][crow * PADt + ccol]);
    wB[1] = smem_u32(&Ws[1][crow * PADt + ccol]);

    float acc[4][4][4];
#pragma unroll
    for (int i = 0; i < 4; i++)
#pragma unroll
        for (int j = 0; j < 4; j++)
#pragma unroll
            for (int r = 0; r < 4; r++) acc[i][j][r] = 0.0f;

    const int T = K / BKt;

    // preload tile 0 into stage 0
    cp16(aB[0],      Ag);
    cp16(aB[0] + 16, Ag + 4);
    cp16(wB[0],      Wg);
    cp16(wB[0] + 16, Wg + 4);
    cp_commit();

    for (int tt = 0; tt < T; tt++) {
        const int cur = tt & 1;
        if (tt + 1 < T) {
            const int nxt = cur ^ 1;
            const int k0 = (tt + 1) * BKt;
            cp16(aB[nxt],      Ag + k0);
            cp16(aB[nxt] + 16, Ag + k0 + 4);
            cp16(wB[nxt],      Wg + k0);
            cp16(wB[nxt] + 16, Wg + k0 + 4);
            cp_commit();
            cp_wait<1>();
        } else {
            cp_wait<0>();
        }
        __syncthreads();

        const float* as = As[cur];
        const float* ws = Ws[cur];
#pragma unroll
        for (int kk = 0; kk < BKt; kk += 8) {
            uint32_t af[4][4], bf[4][2];
#pragma unroll
            for (int i = 0; i < 4; i++) {
                const int r0 = wm + i * 16 + g;
                af[i][0] = f2tf32(as[(r0)     * PADt + kk + t]);
                af[i][1] = f2tf32(as[(r0 + 8) * PADt + kk + t]);
                af[i][2] = f2tf32(as[(r0)     * PADt + kk + t + 4]);
                af[i][3] = f2tf32(as[(r0 + 8) * PADt + kk + t + 4]);
            }
#pragma unroll
            for (int j = 0; j < 4; j++) {
                const int c0 = wn + j * 8 + g;
                bf[j][0] = f2tf32(ws[c0 * PADt + kk + t]);
                bf[j][1] = f2tf32(ws[c0 * PADt + kk + t + 4]);
            }
#pragma unroll
            for (int i = 0; i < 4; i++)
#pragma unroll
                for (int j = 0; j < 4; j++)
                    mma_tf32(acc[i][j], af[i][0], af[i][1], af[i][2], af[i][3],
                             bf[j][0], bf[j][1]);
        }
        __syncthreads();
    }

    // epilogue: add bias, store (float2 per fragment half)
#pragma unroll
    for (int j = 0; j < 4; j++) {
        const int col = bn + wn + j * 8 + 2 * t;
        const float b0 = bias[col];
        const float b1 = bias[col + 1];
#pragma unroll
        for (int i = 0; i < 4; i++) {
            const int row = bm + wm + i * 16 + g;
            float2 v0 = make_float2(acc[i][j][0] + b0, acc[i][j][1] + b1);
            float2 v1 = make_float2(acc[i][j][2] + b0, acc[i][j][3] + b1);
            *(float2*)(C + (size_t)row * ldc + col)       = v0;
            *(float2*)(C + (size_t)(row + 8) * ldc + col) = v1;
        }
    }
}

// ---------------------------------------------------------------------------
// e0[b,:] = sos_embedding
// ---------------------------------------------------------------------------
__global__ void init_e_kernel(float* __restrict__ e, const float* __restrict__ sos)
{
    int idx = blockIdx.x * blockDim.x + threadIdx.x;
    if (idx < Bb * Ee) e[idx] = sos[idx & (Ee - 1)];
}

// ---------------------------------------------------------------------------
// GRU gate fusion, float4-vectorized:
//   r = sigmoid(gi_r + gh_r); z = sigmoid(gi_z + gh_z)
//   n = tanh(gi_n + r * gh_n); h = (1-z)*n + z*h
// ---------------------------------------------------------------------------
__global__ void gru_gates_kernel(const float* __restrict__ gi,
                                 const float* __restrict__ gh,
                                 float* __restrict__ h)
{
    int idx = blockIdx.x * blockDim.x + threadIdx.x;   // over Bb*Hh/4
    if (idx >= Bb * Hh / 4) return;
    int b  = idx / (Hh / 4);
    int j4 = (idx - b * (Hh / 4)) * 4;
    const float* gib = gi + (size_t)b * 3 * Hh;
    const float* ghb = gh + (size_t)b * 3 * Hh;

    float4 gir = *(const float4*)(gib + j4);
    float4 giz = *(const float4*)(gib + Hh + j4);
    float4 gin = *(const float4*)(gib + 2 * Hh + j4);
    float4 ghr = *(const float4*)(ghb + j4);
    float4 ghz = *(const float4*)(ghb + Hh + j4);
    float4 ghn = *(const float4*)(ghb + 2 * Hh + j4);
    float4 hv  = *(float4*)(h + (size_t)b * Hh + j4);

    float4 o;
    {
        float r = 1.0f / (1.0f + expf(-(gir.x + ghr.x)));
        float z = 1.0f / (1.0f + expf(-(giz.x + ghz.x)));
        float n = tanhf(gin.x + r * ghn.x);
        o.x = (1.0f - z) * n + z * hv.x;
    }
    {
        float r = 1.0f / (1.0f + expf(-(gir.y + ghr.y)));
        float z = 1.0f / (1.0f + expf(-(giz.y + ghz.y)));
        float n = tanhf(gin.y + r * ghn.y);
        o.y = (1.0f - z) * n + z * hv.y;
    }
    {
        float r = 1.0f / (1.0f + expf(-(gir.z + ghr.z)));
        float z = 1.0f / (1.0f + expf(-(giz.z + ghz.z)));
        float n = tanhf(gin.z + r * ghn.z);
        o.z = (1.0f - z) * n + z * hv.z;
    }
    {
        float r = 1.0f / (1.0f + expf(-(gir.w + ghr.w)));
        float z = 1.0f / (1.0f + expf(-(giz.w + ghz.w)));
        float n = tanhf(gin.w + r * ghn.w);
        o.w = (1.0f - z) * n + z * hv.w;
    }
    *(float4*)(h + (size_t)b * Hh + j4) = o;
}

// ---------------------------------------------------------------------------
// Gumbel-softmax + entropy, one block (512 threads) per batch row.
// ---------------------------------------------------------------------------
__global__ __launch_bounds__(512) void gumbel_softmax_kernel(
    const float* __restrict__ logits,
    const float* __restrict__ noise,
    float* __restrict__ seq,             // out + l*V (row stride L*V)
    float* __restrict__ ent)             // out + B*L*V + l (row stride L)
{
    __shared__ float sm[16];
    __shared__ float bc;
    const int b = blockIdx.x;
    const int tid = threadIdx.x;

    float u = noise[(size_t)b * Vv + tid];
    float t = logits[(size_t)b * Vv + tid] - logf(-logf(u));

    // max
    float v = t;
#pragma unroll
    for (int o = 16; o; o >>= 1) v = fmaxf(v, __shfl_xor_sync(0xffffffffu, v, o));
    if ((tid & 31) == 0) sm[tid >> 5] = v;
    __syncthreads();
    if (tid < 32) {
        float w = sm[tid & 15];
#pragma unroll
        for (int o = 16; o; o >>= 1) w = fmaxf(w, __shfl_xor_sync(0xffffffffu, w, o));
        if (tid == 0) bc = w;
    }
    __syncthreads();
    const float tmax = bc;
    __syncthreads();

    // sum exp
    float ex = expf(t - tmax);
    v = ex;
#pragma unroll
    for (int o = 16; o; o >>= 1) v += __shfl_xor_sync(0xffffffffu, v, o);
    if ((tid & 31) == 0) sm[tid >> 5] = v;
    __syncthreads();
    if (tid < 32) {
        float w = (tid < 16) ? sm[tid] : 0.0f;
#pragma unroll
        for (int o = 16; o; o >>= 1) w += __shfl_xor_sync(0xffffffffu, w, o);
        if (tid == 0) bc = w;
    }
    __syncthreads();
    const float inv = 1.0f / bc;
    __syncthreads();

    const float p = ex * inv;
    seq[(size_t)b * (Ll * Vv) + tid] = p;

    // entropy
    float el = p * fmaxf(log2f(p), MIN_REAL_F);
    v = el;
#pragma unroll
    for (int o = 16; o; o >>= 1) v += __shfl_xor_sync(0xffffffffu, v, o);
    if ((tid & 31) == 0) sm[tid >> 5] = v;
    __syncthreads();
    if (tid < 32) {
        float w = (tid < 16) ? sm[tid] : 0.0f;
#pragma unroll
        for (int o = 16; o; o >>= 1) w += __shfl_xor_sync(0xffffffffu, w, o);
        if (tid == 0) ent[(size_t)b * Ll] = -w;
    }
}

// ---------------------------------------------------------------------------
// Host launcher
// ---------------------------------------------------------------------------
extern "C" void kernel_launch(void* const* d_in, const int* in_sizes, int n_in,
                              void* d_out, int out_size)
{
    const float* x       = (const float*)d_in[0];
    const float* noise   = (const float*)d_in[1];
    const float* W_agent = (const float*)d_in[2];
    const float* b_agent = (const float*)d_in[3];
    const float* W_ih    = (const float*)d_in[4];
    const float* W_hh    = (const float*)d_in[5];
    const float* b_ih    = (const float*)d_in[6];
    const float* b_hh    = (const float*)d_in[7];
    const float* W_out   = (const float*)d_in[8];
    const float* b_out   = (const float*)d_in[9];
    const float* W_emb   = (const float*)d_in[10];
    const float* b_emb   = (const float*)d_in[11];
    const float* sos     = (const float*)d_in[12];

    float* out = (float*)d_out;
    float* seq = out;                              // [B,L,V]
    float* ent = out + (size_t)Bb * Ll * Vv;       // [B,L]

    float *h, *e, *gi, *gh, *logits;
    cudaGetSymbolAddress((void**)&h,      g_h);
    cudaGetSymbolAddress((void**)&e,      g_e);
    cudaGetSymbolAddress((void**)&gi,     g_gi);
    cudaGetSymbolAddress((void**)&gh,     g_gh);
    cudaGetSymbolAddress((void**)&logits, g_logits);

    const dim3 blk(256);

    // h0 = x @ W_agent^T + b_agent   (N=512, K=512)
    tgemm_nt<<<dim3(Hh / BNt, Bb / BMt), blk>>>(x, W_agent, b_agent, h, DIN, DIN, Hh);
    init_e_kernel<<<(Bb * Ee + 255) / 256, 256>>>(e, sos);

    for (int l = 0; l < Ll; l++) {
        // gi = e @ W_ih^T + b_ih   (N=1536, K=256)
        tgemm_nt<<<dim3(3 * Hh / BNt, Bb / BMt), blk>>>(e, W_ih, b_ih, gi, Ee, Ee, 3 * Hh);
        // gh = h @ W_hh^T + b_hh   (N=1536, K=512)
        tgemm_nt<<<dim3(3 * Hh / BNt, Bb / BMt), blk>>>(h, W_hh, b_hh, gh, Hh, Hh, 3 * Hh);
        // h = GRU(gi, gh, h)
        gru_gates_kernel<<<(Bb * Hh / 4 + 255) / 256, 256>>>(gi, gh, h);
        // logits = h @ W_out^T + b_out   (N=512, K=512)
        tgemm_nt<<<dim3(Vv / BNt, Bb / BMt), blk>>>(h, W_out, b_out, logits, Hh, Hh, Vv);
        // sample + entropy
        gumbel_softmax_kernel<<<Bb, 512>>>(logits,
                                           noise + (size_t)l * Bb * Vv,
                                           seq + (size_t)l * Vv,
                                           ent + l);
        // e = sample @ W_emb^T + b_emb   (N=256, K=512, lda = L*V)
        tgemm_nt<<<dim3(Ee / BNt, Bb / BMt), blk>>>(seq + (size_t)l * Vv, W_emb, b_emb, e,
                                                    Vv, Ll * Vv, Ee);
    }
    (void)in_sizes; (void)n_in; (void)out_size;
}

// round 3
// speedup vs baseline: 5.5797x; 1.8973x over previous
#include <cuda_runtime.h>
#include <cuda_bf16.h>
#include <math.h>
#include <stdint.h>

// Problem constants: B=4096, D_IN=512, H=512, E=256, V=512, L=32
#define Bb   4096
#define DIN  512
#define Hh   512
#define Ee   256
#define Vv   512
#define Ll   32
#define MIN_REAL_F (-3.4028234663852886e+38f)

// Persistent state / scratch (no allocations allowed)
__device__ float g_h[Bb * Hh];
__device__ float g_gi[Bb * 3 * Hh];
__device__ float g_gh[Bb * 3 * Hh];
__device__ float g_logits[Bb * Vv];

// bf16 copies (GEMM operands)
__device__ __nv_bfloat16 g_xb[Bb * DIN];
__device__ __nv_bfloat16 g_Wab[Hh * DIN];
__device__ __nv_bfloat16 g_Wihb[3 * Hh * Ee];
__device__ __nv_bfloat16 g_Whhb[3 * Hh * Hh];
__device__ __nv_bfloat16 g_Woutb[Vv * Hh];
__device__ __nv_bfloat16 g_Wembb[Ee * Vv];
__device__ __nv_bfloat16 g_hb[Bb * Hh];
__device__ __nv_bfloat16 g_eb[Bb * Ee];
__device__ __nv_bfloat16 g_sampb[Bb * Vv];

// ---------------------------------------------------------------------------
// PTX helpers
// ---------------------------------------------------------------------------
__device__ __forceinline__ uint32_t smem_u32(const void* p) {
    return (uint32_t)__cvta_generic_to_shared(p);
}
__device__ __forceinline__ void cp16(uint32_t s, const void* g) {
    asm volatile("cp.async.cg.shared.global [%0], [%1], 16;\n" :: "r"(s), "l"(g));
}
__device__ __forceinline__ void cp_commit() {
    asm volatile("cp.async.commit_group;\n");
}
template<int N> __device__ __forceinline__ void cp_wait() {
    asm volatile("cp.async.wait_group %0;\n" :: "n"(N));
}
__device__ __forceinline__ void ldsm4(uint32_t& r0, uint32_t& r1,
                                      uint32_t& r2, uint32_t& r3, uint32_t a) {
    asm volatile("ldmatrix.sync.aligned.m8n8.x4.shared.b16 {%0,%1,%2,%3}, [%4];\n"
                 : "=r"(r0), "=r"(r1), "=r"(r2), "=r"(r3) : "r"(a));
}
__device__ __forceinline__ void mma_bf16(float c[4], const uint32_t a[4],
                                         uint32_t b0, uint32_t b1) {
    asm volatile(
        "mma.sync.aligned.m16n8k16.row.col.f32.bf16.bf16.f32 "
        "{%0,%1,%2,%3}, {%4,%5,%6,%7}, {%8,%9}, {%0,%1,%2,%3};\n"
        : "+f"(c[0]), "+f"(c[1]), "+f"(c[2]), "+f"(c[3])
        : "r"(a[0]), "r"(a[1]), "r"(a[2]), "r"(a[3]), "r"(b0), "r"(b1));
}

// ---------------------------------------------------------------------------
// bf16 GEMM:  out[M,N] = A[M,K](bf16) @ W[N,K](bf16)^T + bias
// BK=32 (64B rows), 3-stage cp.async, XOR-swizzled smem, ldmatrix feeds.
// 256 threads = 8 warps arranged (BM/WM) x (BN/WN). C (fp32) and/or Cb (bf16)
// outputs, either may be null.
// ---------------------------------------------------------------------------
template<int BM, int BN, int WM, int WN>
__global__ __launch_bounds__(256, 2) void bgemm(
    const __nv_bfloat16* __restrict__ A, const __nv_bfloat16* __restrict__ W,
    const float* __restrict__ bias, float* __restrict__ C,
    __nv_bfloat16* __restrict__ Cb, int K, int lda, int ldc)
{
    constexpr int BK = 32;
    constexpr int STAGES = 3;
    constexpr int WARPS_M = BM / WM;
    constexpr int MI = WM / 16;      // m16 blocks per warp
    constexpr int NJ = WN / 8;       // n8 blocks per warp
    constexpr int NJ2 = WN / 16;     // ldmatrix.x4 groups on B
    constexpr int ACH = BM * 4 / 256;  // 16B chunks per thread for A stage
    constexpr int WCH = BN * 4 / 256;

    __shared__ __nv_bfloat16 As[STAGES][BM * BK];
    __shared__ __nv_bfloat16 Ws[STAGES][BN * BK];

    const int tid  = threadIdx.x;
    const int warp = tid >> 5;
    const int lane = tid & 31;
    const int g = lane >> 2;
    const int t = lane & 3;
    const int wm = (warp % WARPS_M) * WM;
    const int wn = (warp / WARPS_M) * WN;
    const int bm = blockIdx.y * BM;
    const int bn = blockIdx.x * BN;

    const int lrow = lane & 15;      // ldmatrix row within 16-block
    const int lsel = lane >> 4;      // ldmatrix k-chunk selector (0/1)

    float acc[MI][NJ][4];
#pragma unroll
    for (int i = 0; i < MI; i++)
#pragma unroll
        for (int j = 0; j < NJ; j++)
#pragma unroll
            for (int r = 0; r < 4; r++) acc[i][j][r] = 0.0f;

    const int T = K / BK;

    // stage loader: 16B chunk id -> (row, chunk), swizzle chunk ^= (row>>1)&3
    auto load_stage = [&](int s, int kt) {
        const int k0 = kt * BK;
#pragma unroll
        for (int i = 0; i < ACH; i++) {
            int cid = tid + i * 256;
            int r = cid >> 2, c = cid & 3;
            cp16(smem_u32(&As[s][r * BK + ((c ^ ((r >> 1) & 3)) << 3)]),
                 A + (size_t)(bm + r) * lda + k0 + c * 8);
        }
#pragma unroll
        for (int i = 0; i < WCH; i++) {
            int cid = tid + i * 256;
            int r = cid >> 2, c = cid & 3;
            cp16(smem_u32(&Ws[s][r * BK + ((c ^ ((r >> 1) & 3)) << 3)]),
                 W + (size_t)(bn + r) * K + k0 + c * 8);
        }
    };

    load_stage(0, 0); cp_commit();
    load_stage(1, 1); cp_commit();

    for (int kt = 0; kt < T; kt++) {
        cp_wait<STAGES - 2>();
        __syncthreads();
        const int pf = kt + STAGES - 1;
        if (pf < T) load_stage(pf % STAGES, pf);
        cp_commit();

        const __nv_bfloat16* as = As[kt % STAGES];
        const __nv_bfloat16* ws = Ws[kt % STAGES];
#pragma unroll
        for (int kh = 0; kh < 2; kh++) {
            const int cch = kh * 2 + lsel;   // 16B chunk index for this lane
            uint32_t af[MI][4];
#pragma unroll
            for (int i = 0; i < MI; i++) {
                int row = wm + i * 16 + lrow;
                ldsm4(af[i][0], af[i][1], af[i][2], af[i][3],
                      smem_u32(&as[row * BK + ((cch ^ ((row >> 1) & 3)) << 3)]));
            }
            uint32_t bfr[NJ2][4];
#pragma unroll
            for (int j = 0; j < NJ2; j++) {
                int row = wn + j * 16 + lrow;
                ldsm4(bfr[j][0], bfr[j][1], bfr[j][2], bfr[j][3],
                      smem_u32(&ws[row * BK + ((cch ^ ((row >> 1) & 3)) << 3)]));
            }
#pragma unroll
            for (int i = 0; i < MI; i++)
#pragma unroll
                for (int j = 0; j < NJ2; j++) {
                    mma_bf16(acc[i][2 * j],     af[i], bfr[j][0], bfr[j][2]);
                    mma_bf16(acc[i][2 * j + 1], af[i], bfr[j][1], bfr[j][3]);
                }
        }
    }

    // epilogue: bias + dual store
#pragma unroll
    for (int j = 0; j < NJ; j++) {
        const int col = bn + wn + j * 8 + 2 * t;
        const float b0 = bias[col];
        const float b1 = bias[col + 1];
#pragma unroll
        for (int i = 0; i < MI; i++) {
            const int row = bm + wm + i * 16 + g;
            float v00 = acc[i][j][0] + b0, v01 = acc[i][j][1] + b1;
            float v10 = acc[i][j][2] + b0, v11 = acc[i][j][3] + b1;
            if (C) {
                *(float2*)(C + (size_t)row * ldc + col)       = make_float2(v00, v01);
                *(float2*)(C + (size_t)(row + 8) * ldc + col) = make_float2(v10, v11);
            }
            if (Cb) {
                *(__nv_bfloat162*)(Cb + (size_t)row * ldc + col) =
                    __floats2bfloat162_rn(v00, v01);
                *(__nv_bfloat162*)(Cb + (size_t)(row + 8) * ldc + col) =
                    __floats2bfloat162_rn(v10, v11);
            }
        }
    }
}

// ---------------------------------------------------------------------------
// fp32 -> bf16 conversion (vectorized), n must be divisible by 4
// ---------------------------------------------------------------------------
__global__ void f2b_kernel(const float* __restrict__ in,
                           __nv_bfloat16* __restrict__ out, int n4)
{
    int i = blockIdx.x * blockDim.x + threadIdx.x;
    if (i < n4) {
        float4 v = ((const float4*)in)[i];
        ((__nv_bfloat162*)out)[2 * i]     = __floats2bfloat162_rn(v.x, v.y);
        ((__nv_bfloat162*)out)[2 * i + 1] = __floats2bfloat162_rn(v.z, v.w);
    }
}

// e0[b,:] = bf16(sos_embedding)
__global__ void init_e_kernel(__nv_bfloat16* __restrict__ eb,
                              const float* __restrict__ sos)
{
    int idx = blockIdx.x * blockDim.x + threadIdx.x;
    if (idx < Bb * Ee) eb[idx] = __float2bfloat16(sos[idx & (Ee - 1)]);
}

// ---------------------------------------------------------------------------
// GRU gates (float4), dual-writes h (fp32) and hb (bf16)
// ---------------------------------------------------------------------------
__global__ void gru_gates_kernel(const float* __restrict__ gi,
                                 const float* __restrict__ gh,
                                 float* __restrict__ h,
                                 __nv_bfloat16* __restrict__ hb)
{
    int idx = blockIdx.x * blockDim.x + threadIdx.x;
    if (idx >= Bb * Hh / 4) return;
    int b  = idx / (Hh / 4);
    int j4 = (idx - b * (Hh / 4)) * 4;
    const float* gib = gi + (size_t)b * 3 * Hh;
    const float* ghb = gh + (size_t)b * 3 * Hh;

    float4 gir = *(const float4*)(gib + j4);
    float4 giz = *(const float4*)(gib + Hh + j4);
    float4 gin = *(const float4*)(gib + 2 * Hh + j4);
    float4 ghr = *(const float4*)(ghb + j4);
    float4 ghz = *(const float4*)(ghb + Hh + j4);
    float4 ghn = *(const float4*)(ghb + 2 * Hh + j4);
    float4 hv  = *(float4*)(h + (size_t)b * Hh + j4);

    float4 o;
#define GATE(c) { \
        float r = 1.0f / (1.0f + expf(-(gir.c + ghr.c))); \
        float z = 1.0f / (1.0f + expf(-(giz.c + ghz.c))); \
        float n = tanhf(gin.c + r * ghn.c); \
        o.c = (1.0f - z) * n + z * hv.c; }
    GATE(x) GATE(y) GATE(z) GATE(w)
#undef GATE
    *(float4*)(h + (size_t)b * Hh + j4) = o;
    __nv_bfloat162* hb2 = (__nv_bfloat162*)(hb + (size_t)b * Hh + j4);
    hb2[0] = __floats2bfloat162_rn(o.x, o.y);
    hb2[1] = __floats2bfloat162_rn(o.z, o.w);
}

// ---------------------------------------------------------------------------
// Gumbel-softmax + entropy; writes seq (fp32, strided into d_out), sampb (bf16)
// ---------------------------------------------------------------------------
__global__ __launch_bounds__(512) void gumbel_softmax_kernel(
    const float* __restrict__ logits,
    const float* __restrict__ noise,
    float* __restrict__ seq,                 // out + l*V (row stride L*V)
    __nv_bfloat16* __restrict__ sampb,       // [B,V]
    float* __restrict__ ent)                 // out + B*L*V + l (row stride L)
{
    __shared__ float sm[16];
    __shared__ float bc;
    const int b = blockIdx.x;
    const int tid = threadIdx.x;

    float u = noise[(size_t)b * Vv + tid];
    float t = logits[(size_t)b * Vv + tid] - logf(-logf(u));

    float v = t;
#pragma unroll
    for (int o = 16; o; o >>= 1) v = fmaxf(v, __shfl_xor_sync(0xffffffffu, v, o));
    if ((tid & 31) == 0) sm[tid >> 5] = v;
    __syncthreads();
    if (tid < 32) {
        float w = sm[tid & 15];
#pragma unroll
        for (int o = 16; o; o >>= 1) w = fmaxf(w, __shfl_xor_sync(0xffffffffu, w, o));
        if (tid == 0) bc = w;
    }
    __syncthreads();
    const float tmax = bc;
    __syncthreads();

    float ex = expf(t - tmax);
    v = ex;
#pragma unroll
    for (int o = 16; o; o >>= 1) v += __shfl_xor_sync(0xffffffffu, v, o);
    if ((tid & 31) == 0) sm[tid >> 5] = v;
    __syncthreads();
    if (tid < 32) {
        float w = (tid < 16) ? sm[tid] : 0.0f;
#pragma unroll
        for (int o = 16; o; o >>= 1) w += __shfl_xor_sync(0xffffffffu, w, o);
        if (tid == 0) bc = w;
    }
    __syncthreads();
    const float inv = 1.0f / bc;
    __syncthreads();

    const float p = ex * inv;
    seq[(size_t)b * (Ll * Vv) + tid] = p;
    sampb[(size_t)b * Vv + tid] = __float2bfloat16(p);

    float el = p * fmaxf(log2f(p), MIN_REAL_F);
    v = el;
#pragma unroll
    for (int o = 16; o; o >>= 1) v += __shfl_xor_sync(0xffffffffu, v, o);
    if ((tid & 31) == 0) sm[tid >> 5] = v;
    __syncthreads();
    if (tid < 32) {
        float w = (tid < 16) ? sm[tid] : 0.0f;
#pragma unroll
        for (int o = 16; o; o >>= 1) w += __shfl_xor_sync(0xffffffffu, w, o);
        if (tid == 0) ent[(size_t)b * Ll] = -w;
    }
}

// ---------------------------------------------------------------------------
// Host launcher
// ---------------------------------------------------------------------------
extern "C" void kernel_launch(void* const* d_in, const int* in_sizes, int n_in,
                              void* d_out, int out_size)
{
    const float* x       = (const float*)d_in[0];
    const float* noise   = (const float*)d_in[1];
    const float* b_agent = (const float*)d_in[3];
    const float* b_ih    = (const float*)d_in[6];
    const float* b_hh    = (const float*)d_in[7];
    const float* b_out   = (const float*)d_in[9];
    const float* b_emb   = (const float*)d_in[11];
    const float* sos     = (const float*)d_in[12];

    float* out = (float*)d_out;
    float* seq = out;                              // [B,L,V]
    float* ent = out + (size_t)Bb * Ll * Vv;       // [B,L]

    float *h, *gi, *gh, *logits;
    __nv_bfloat16 *xb, *Wab, *Wihb, *Whhb, *Woutb, *Wembb, *hb, *eb, *sampb;
    cudaGetSymbolAddress((void**)&h,      g_h);
    cudaGetSymbolAddress((void**)&gi,     g_gi);
    cudaGetSymbolAddress((void**)&gh,     g_gh);
    cudaGetSymbolAddress((void**)&logits, g_logits);
    cudaGetSymbolAddress((void**)&xb,     g_xb);
    cudaGetSymbolAddress((void**)&Wab,    g_Wab);
    cudaGetSymbolAddress((void**)&Wihb,   g_Wihb);
    cudaGetSymbolAddress((void**)&Whhb,   g_Whhb);
    cudaGetSymbolAddress((void**)&Woutb,  g_Woutb);
    cudaGetSymbolAddress((void**)&Wembb,  g_Wembb);
    cudaGetSymbolAddress((void**)&hb,     g_hb);
    cudaGetSymbolAddress((void**)&eb,     g_eb);
    cudaGetSymbolAddress((void**)&sampb,  g_sampb);

    // convert inputs / weights to bf16
    auto conv = [&](const void* src, __nv_bfloat16* dst, int n) {
        f2b_kernel<<<(n / 4 + 255) / 256, 256>>>((const float*)src, dst, n / 4);
    };
    conv(x,        xb,    Bb * DIN);
    conv(d_in[2],  Wab,   Hh * DIN);
    conv(d_in[4],  Wihb,  3 * Hh * Ee);
    conv(d_in[5],  Whhb,  3 * Hh * Hh);
    conv(d_in[8],  Woutb, Vv * Hh);
    conv(d_in[10], Wembb, Ee * Vv);

    // h0 = x @ W_agent^T + b_agent  (N=512, K=512) -> h fp32 + hb bf16
    bgemm<64, 128, 32, 32><<<dim3(Hh / 128, Bb / 64), 256>>>(
        xb, Wab, b_agent, h, hb, DIN, DIN, Hh);
    init_e_kernel<<<(Bb * Ee + 255) / 256, 256>>>(eb, sos);

    for (int l = 0; l < Ll; l++) {
        // gi = e @ W_ih^T + b_ih   (N=1536, K=256)
        bgemm<128, 128, 64, 32><<<dim3(3 * Hh / 128, Bb / 128), 256>>>(
            eb, Wihb, b_ih, gi, (__nv_bfloat16*)nullptr, Ee, Ee, 3 * Hh);
        // gh = h @ W_hh^T + b_hh   (N=1536, K=512)
        bgemm<128, 128, 64, 32><<<dim3(3 * Hh / 128, Bb / 128), 256>>>(
            hb, Whhb, b_hh, gh, (__nv_bfloat16*)nullptr, Hh, Hh, 3 * Hh);
        // h = GRU(gi, gh, h) -> h fp32 + hb bf16
        gru_gates_kernel<<<(Bb * Hh / 4 + 255) / 256, 256>>>(gi, gh, h, hb);
        // logits = h @ W_out^T + b_out  (N=512, K=512)
        bgemm<64, 128, 32, 32><<<dim3(Vv / 128, Bb / 64), 256>>>(
            hb, Woutb, b_out, logits, (__nv_bfloat16*)nullptr, Hh, Hh, Vv);
        // sample + entropy (fp32 into d_out, bf16 copy for emb GEMM)
        gumbel_softmax_kernel<<<Bb, 512>>>(logits,
                                           noise + (size_t)l * Bb * Vv,
                                           seq + (size_t)l * Vv, sampb,
                                           ent + l);
        // e = sample @ W_emb^T + b_emb  (N=256, K=512) -> eb bf16 only
        bgemm<64, 128, 32, 32><<<dim3(Ee / 128, Bb / 64), 256>>>(
            sampb, Wembb, b_emb, (float*)nullptr, eb, Vv, Vv, Ee);
    }
    (void)in_sizes; (void)n_in; (void)out_size;
}

// round 5
// speedup vs baseline: 6.9579x; 1.2470x over previous
#include <cuda_runtime.h>
#include <cuda_bf16.h>
#include <math.h>
#include <stdint.h>

// Problem constants: B=4096, D_IN=512, H=512, E=256, V=512, L=32
#define Bb   4096
#define DIN  512
#define Hh   512
#define Ee   256
#define Vv   512
#define Ll   32
#define MIN_REAL_F (-3.4028234663852886e+38f)

// Persistent scratch (device globals; no allocations allowed)
__device__ float g_h[Bb * Hh];
__device__ float g_logits[Bb * Vv];

__device__ __nv_bfloat16 g_xb[Bb * DIN];
__device__ __nv_bfloat16 g_Wab[Hh * DIN];
__device__ __nv_bfloat16 g_Wihb[3 * Hh * Ee];
__device__ __nv_bfloat16 g_Whhb[3 * Hh * Hh];
__device__ __nv_bfloat16 g_Woutb[Vv * Hh];
__device__ __nv_bfloat16 g_Wembb[Ee * Vv];
__device__ __nv_bfloat16 g_hb[Bb * Hh];
__device__ __nv_bfloat16 g_eb[Bb * Ee];
__device__ __nv_bfloat16 g_gib[Bb * 3 * Hh];
__device__ __nv_bfloat16 g_ghb[Bb * 3 * Hh];
__device__ __nv_bfloat16 g_sampb[Bb * Vv];

// ---------------------------------------------------------------------------
// PTX helpers
// ---------------------------------------------------------------------------
__device__ __forceinline__ uint32_t smem_u32(const void* p) {
    return (uint32_t)__cvta_generic_to_shared(p);
}
__device__ __forceinline__ void cp16(uint32_t s, const void* g) {
    asm volatile("cp.async.cg.shared.global [%0], [%1], 16;\n" :: "r"(s), "l"(g));
}
__device__ __forceinline__ void cp_commit() {
    asm volatile("cp.async.commit_group;\n");
}
template<int N> __device__ __forceinline__ void cp_wait() {
    asm volatile("cp.async.wait_group %0;\n" :: "n"(N));
}
__device__ __forceinline__ void ldsm4(uint32_t& r0, uint32_t& r1,
                                      uint32_t& r2, uint32_t& r3, uint32_t a) {
    asm volatile("ldmatrix.sync.aligned.m8n8.x4.shared.b16 {%0,%1,%2,%3}, [%4];\n"
                 : "=r"(r0), "=r"(r1), "=r"(r2), "=r"(r3) : "r"(a));
}
__device__ __forceinline__ void mma_bf16(float c[4], const uint32_t a[4],
                                         uint32_t b0, uint32_t b1) {
    asm volatile(
        "mma.sync.aligned.m16n8k16.row.col.f32.bf16.bf16.f32 "
        "{%0,%1,%2,%3}, {%4,%5,%6,%7}, {%8,%9}, {%0,%1,%2,%3};\n"
        : "+f"(c[0]), "+f"(c[1]), "+f"(c[2]), "+f"(c[3])
        : "r"(a[0]), "r"(a[1]), "r"(a[2]), "r"(a[3]), "r"(b0), "r"(b1));
}

// ---------------------------------------------------------------------------
// bf16 HMMA GEMM:  out[M,N] = A[M,K] @ W[N,K]^T + bias
// BK=64 (128B rows), 3-stage cp.async, swizzle chunk c^(r&7).
// 256 threads = 8 warps (BM/WM x BN/WN). grid.z selects between two arg sets.
// ---------------------------------------------------------------------------
struct GemmArgs {
    const __nv_bfloat16* A;
    const __nv_bfloat16* W;
    const float* bias;
    float* C;                 // nullable fp32 out
    __nv_bfloat16* Cb;        // nullable bf16 out
    int lda;
    int ldc;
};

template<int BM, int BN, int WM, int WN>
__global__ __launch_bounds__(256) void tcb_gemm(GemmArgs a0, GemmArgs a1,
                                                int K0, int K1)
{
    constexpr int BK = 64;            // 128 bytes per row
    constexpr int STAGES = 3;
    constexpr int WARPS_M = BM / WM;
    constexpr int MI = WM / 16;
    constexpr int NJ = WN / 8;
    constexpr int NJ2 = WN / 16;
    constexpr int ACH = BM * 8 / 256;   // 16B chunks per thread (A)
    constexpr int WCH = BN * 8 / 256;
    constexpr int ABYTES = BM * 128;    // bytes per A stage
    constexpr int WBYTES = BN * 128;

    extern __shared__ char dsm[];
    const GemmArgs ga = blockIdx.z ? a1 : a0;
    const int K = blockIdx.z ? K1 : K0;

    const uint32_t sbase = smem_u32(dsm);
    const uint32_t aBase = sbase;                       // STAGES * ABYTES
    const uint32_t wBase = sbase + STAGES * ABYTES;     // STAGES * WBYTES

    const int tid  = threadIdx.x;
    const int warp = tid >> 5;
    const int lane = tid & 31;
    const int g = lane >> 2;
    const int t = lane & 3;
    const int wm = (warp % WARPS_M) * WM;
    const int wn = (warp / WARPS_M) * WN;
    const int bm = blockIdx.y * BM;
    const int bn = blockIdx.x * BN;
    const int lrow = lane & 15;
    const int lsel = lane >> 4;

    float acc[MI][NJ][4];
#pragma unroll
    for (int i = 0; i < MI; i++)
#pragma unroll
        for (int j = 0; j < NJ; j++)
#pragma unroll
            for (int r = 0; r < 4; r++) acc[i][j][r] = 0.0f;

    const int T = K / BK;

    auto load_stage = [&](int s, int k0) {
        const __nv_bfloat16* Ap = ga.A + (size_t)bm * ga.lda + k0;
        const __nv_bfloat16* Wp = ga.W + (size_t)bn * K + k0;
        const uint32_t as = aBase + s * ABYTES;
        const uint32_t ws = wBase + s * WBYTES;
#pragma unroll
        for (int i = 0; i < ACH; i++) {
            int cid = tid + i * 256;
            int r = cid >> 3, c = cid & 7;
            cp16(as + r * 128 + ((c ^ (r & 7)) << 4),
                 Ap + (size_t)r * ga.lda + c * 8);
        }
#pragma unroll
        for (int i = 0; i < WCH; i++) {
            int cid = tid + i * 256;
            int r = cid >> 3, c = cid & 7;
            cp16(ws + r * 128 + ((c ^ (r & 7)) << 4),
                 Wp + (size_t)r * K + c * 8);
        }
    };

    load_stage(0, 0);  cp_commit();
    if (T > 1) load_stage(1, BK);
    cp_commit();

    for (int kt = 0; kt < T; kt++) {
        const int s = kt % STAGES;
        cp_wait<1>();
        __syncthreads();
        const int pf = kt + 2;
        if (pf < T) load_stage(pf % STAGES, pf * BK);
        cp_commit();

        const uint32_t as = aBase + s * ABYTES;
        const uint32_t ws = wBase + s * WBYTES;
#pragma unroll
        for (int kh = 0; kh < BK / 16; kh++) {
            const int cch = kh * 2 + lsel;
            uint32_t af[MI][4];
#pragma unroll
            for (int i = 0; i < MI; i++) {
                int row = wm + i * 16 + lrow;
                ldsm4(af[i][0], af[i][1], af[i][2], af[i][3],
                      as + row * 128 + ((cch ^ (row & 7)) << 4));
            }
            uint32_t bfr[NJ2][4];
#pragma unroll
            for (int j = 0; j < NJ2; j++) {
                int row = wn + j * 16 + lrow;
                ldsm4(bfr[j][0], bfr[j][1], bfr[j][2], bfr[j][3],
                      ws + row * 128 + ((cch ^ (row & 7)) << 4));
            }
#pragma unroll
            for (int i = 0; i < MI; i++)
#pragma unroll
                for (int j = 0; j < NJ2; j++) {
                    mma_bf16(acc[i][2 * j],     af[i], bfr[j][0], bfr[j][2]);
                    mma_bf16(acc[i][2 * j + 1], af[i], bfr[j][1], bfr[j][3]);
                }
        }
        __syncthreads();
    }

    // epilogue
#pragma unroll
    for (int j = 0; j < NJ; j++) {
        const int col = bn + wn + j * 8 + 2 * t;
        const float b0 = ga.bias[col];
        const float b1 = ga.bias[col + 1];
#pragma unroll
        for (int i = 0; i < MI; i++) {
            const int row = bm + wm + i * 16 + g;
            float v00 = acc[i][j][0] + b0, v01 = acc[i][j][1] + b1;
            float v10 = acc[i][j][2] + b0, v11 = acc[i][j][3] + b1;
            if (ga.C) {
                *(float2*)(ga.C + (size_t)row * ga.ldc + col)       = make_float2(v00, v01);
                *(float2*)(ga.C + (size_t)(row + 8) * ga.ldc + col) = make_float2(v10, v11);
            }
            if (ga.Cb) {
                *(__nv_bfloat162*)(ga.Cb + (size_t)row * ga.ldc + col) =
                    __floats2bfloat162_rn(v00, v01);
                *(__nv_bfloat162*)(ga.Cb + (size_t)(row + 8) * ga.ldc + col) =
                    __floats2bfloat162_rn(v10, v11);
            }
        }
    }
}

// ---------------------------------------------------------------------------
// fp32 -> bf16 conversion
// ---------------------------------------------------------------------------
__global__ void f2b_kernel(const float* __restrict__ in,
                           __nv_bfloat16* __restrict__ out, int n4)
{
    int i = blockIdx.x * blockDim.x + threadIdx.x;
    if (i < n4) {
        float4 v = ((const float4*)in)[i];
        ((__nv_bfloat162*)out)[2 * i]     = __floats2bfloat162_rn(v.x, v.y);
        ((__nv_bfloat162*)out)[2 * i + 1] = __floats2bfloat162_rn(v.z, v.w);
    }
}

__global__ void init_e_kernel(__nv_bfloat16* __restrict__ eb,
                              const float* __restrict__ sos)
{
    int idx = blockIdx.x * blockDim.x + threadIdx.x;
    if (idx < Bb * Ee) eb[idx] = __float2bfloat16(sos[idx & (Ee - 1)]);
}

// ---------------------------------------------------------------------------
// GRU gates (bf16 gi/gh, fp32 h state, dual h/hb write)
// ---------------------------------------------------------------------------
__global__ void gru_gates_kernel(const __nv_bfloat16* __restrict__ gi,
                                 const __nv_bfloat16* __restrict__ gh,
                                 float* __restrict__ h,
                                 __nv_bfloat16* __restrict__ hb)
{
    int idx = blockIdx.x * blockDim.x + threadIdx.x;
    if (idx >= Bb * Hh / 2) return;
    int b  = idx / (Hh / 2);
    int j2 = (idx - b * (Hh / 2)) * 2;

    const __nv_bfloat162* gi2 = (const __nv_bfloat162*)(gi + (size_t)b * 3 * Hh);
    const __nv_bfloat162* gh2 = (const __nv_bfloat162*)(gh + (size_t)b * 3 * Hh);
    float2 ir  = __bfloat1622float2(gi2[j2 >> 1]);
    float2 iz  = __bfloat1622float2(gi2[(Hh + j2) >> 1]);
    float2 inn = __bfloat1622float2(gi2[(2 * Hh + j2) >> 1]);
    float2 hr  = __bfloat1622float2(gh2[j2 >> 1]);
    float2 hz  = __bfloat1622float2(gh2[(Hh + j2) >> 1]);
    float2 hn  = __bfloat1622float2(gh2[(2 * Hh + j2) >> 1]);
    float2 hv  = *(float2*)(h + (size_t)b * Hh + j2);

    float2 o;
    {
        float r = 1.0f / (1.0f + expf(-(ir.x + hr.x)));
        float z = 1.0f / (1.0f + expf(-(iz.x + hz.x)));
        float n = tanhf(inn.x + r * hn.x);
        o.x = (1.0f - z) * n + z * hv.x;
    }
    {
        float r = 1.0f / (1.0f + expf(-(ir.y + hr.y)));
        float z = 1.0f / (1.0f + expf(-(iz.y + hz.y)));
        float n = tanhf(inn.y + r * hn.y);
        o.y = (1.0f - z) * n + z * hv.y;
    }
    *(float2*)(h + (size_t)b * Hh + j2) = o;
    *(__nv_bfloat162*)(hb + (size_t)b * Hh + j2) = __floats2bfloat162_rn(o.x, o.y);
}

// ---------------------------------------------------------------------------
// Gumbel-softmax + entropy, one WARP per batch row (V=512 -> 16 elems/lane).
// Shuffle-only reductions, float4 I/O. 256 threads = 8 rows per block.
// ---------------------------------------------------------------------------
__global__ __launch_bounds__(256) void gumbel_softmax_kernel(
    const float* __restrict__ logits,
    const float* __restrict__ noise,
    float* __restrict__ seq,                 // out + l*V (row stride L*V)
    __nv_bfloat16* __restrict__ sampb,       // [B,V]
    float* __restrict__ ent)                 // out + B*L*V + l (row stride L)
{
    const int warp = threadIdx.x >> 5;
    const int lane = threadIdx.x & 31;
    const int b = blockIdx.x * 8 + warp;

    const float4* lg4 = (const float4*)(logits + (size_t)b * Vv);
    const float4* nz4 = (const float4*)(noise + (size_t)b * Vv);

    float tv[16];
    float m = -INFINITY;
#pragma unroll
    for (int i = 0; i < 4; i++) {
        float4 lv = lg4[i * 32 + lane];
        float4 uv = nz4[i * 32 + lane];
        tv[4 * i + 0] = lv.x - logf(-logf(uv.x));
        tv[4 * i + 1] = lv.y - logf(-logf(uv.y));
        tv[4 * i + 2] = lv.z - logf(-logf(uv.z));
        tv[4 * i + 3] = lv.w - logf(-logf(uv.w));
        m = fmaxf(m, fmaxf(fmaxf(tv[4 * i], tv[4 * i + 1]),
                           fmaxf(tv[4 * i + 2], tv[4 * i + 3])));
    }
#pragma unroll
    for (int o = 16; o; o >>= 1) m = fmaxf(m, __shfl_xor_sync(0xffffffffu, m, o));

    float s = 0.0f;
#pragma unroll
    for (int i = 0; i < 16; i++) { tv[i] = expf(tv[i] - m); s += tv[i]; }
#pragma unroll
    for (int o = 16; o; o >>= 1) s += __shfl_xor_sync(0xffffffffu, s, o);
    const float inv = 1.0f / s;

    float4* sq4 = (float4*)(seq + (size_t)b * (Ll * Vv));
    __nv_bfloat162* sb2 = (__nv_bfloat162*)(sampb + (size_t)b * Vv);
    float el = 0.0f;
#pragma unroll
    for (int i = 0; i < 4; i++) {
        float p0 = tv[4 * i] * inv,     p1 = tv[4 * i + 1] * inv;
        float p2 = tv[4 * i + 2] * inv, p3 = tv[4 * i + 3] * inv;
        sq4[i * 32 + lane] = make_float4(p0, p1, p2, p3);
        sb2[2 * (i * 32 + lane)]     = __floats2bfloat162_rn(p0, p1);
        sb2[2 * (i * 32 + lane) + 1] = __floats2bfloat162_rn(p2, p3);
        el += p0 * fmaxf(log2f(p0), MIN_REAL_F) + p1 * fmaxf(log2f(p1), MIN_REAL_F)
            + p2 * fmaxf(log2f(p2), MIN_REAL_F) + p3 * fmaxf(log2f(p3), MIN_REAL_F);
    }
#pragma unroll
    for (int o = 16; o; o >>= 1) el += __shfl_xor_sync(0xffffffffu, el, o);
    if (lane == 0) ent[(size_t)b * Ll] = -el;
}

// ---------------------------------------------------------------------------
// Host launcher
// ---------------------------------------------------------------------------
#define SMEM_BIG  ((3 * (128 + 128) * 128))   // 98304
#define SMEM_HALF ((3 * (64 + 128) * 128))    // 73728

extern "C" void kernel_launch(void* const* d_in, const int* in_sizes, int n_in,
                              void* d_out, int out_size)
{
    const float* x       = (const float*)d_in[0];
    const float* noise   = (const float*)d_in[1];
    const float* b_agent = (const float*)d_in[3];
    const float* b_ih    = (const float*)d_in[6];
    const float* b_hh    = (const float*)d_in[7];
    const float* b_out   = (const float*)d_in[9];
    const float* b_emb   = (const float*)d_in[11];
    const float* sos     = (const float*)d_in[12];

    float* out = (float*)d_out;
    float* seq = out;                              // [B,L,V]
    float* ent = out + (size_t)Bb * Ll * Vv;       // [B,L]

    float *h, *logits;
    __nv_bfloat16 *xb, *Wab, *Wihb, *Whhb, *Woutb, *Wembb;
    __nv_bfloat16 *hb, *eb, *gib, *ghb, *sampb;
    cudaGetSymbolAddress((void**)&h,      g_h);
    cudaGetSymbolAddress((void**)&logits, g_logits);
    cudaGetSymbolAddress((void**)&xb,     g_xb);
    cudaGetSymbolAddress((void**)&Wab,    g_Wab);
    cudaGetSymbolAddress((void**)&Wihb,   g_Wihb);
    cudaGetSymbolAddress((void**)&Whhb,   g_Whhb);
    cudaGetSymbolAddress((void**)&Woutb,  g_Woutb);
    cudaGetSymbolAddress((void**)&Wembb,  g_Wembb);
    cudaGetSymbolAddress((void**)&hb,     g_hb);
    cudaGetSymbolAddress((void**)&eb,     g_eb);
    cudaGetSymbolAddress((void**)&gib,    g_gib);
    cudaGetSymbolAddress((void**)&ghb,    g_ghb);
    cudaGetSymbolAddress((void**)&sampb,  g_sampb);

    cudaFuncSetAttribute((const void*)tcb_gemm<128, 128, 64, 32>,
                         cudaFuncAttributeMaxDynamicSharedMemorySize, SMEM_BIG);
    cudaFuncSetAttribute((const void*)tcb_gemm<64, 128, 32, 32>,
                         cudaFuncAttributeMaxDynamicSharedMemorySize, SMEM_HALF);

    auto conv = [&](const void* src, __nv_bfloat16* dst, int n) {
        f2b_kernel<<<(n / 4 + 255) / 256, 256>>>((const float*)src, dst, n / 4);
    };
    conv(x,        xb,    Bb * DIN);
    conv(d_in[2],  Wab,   Hh * DIN);
    conv(d_in[4],  Wihb,  3 * Hh * Ee);
    conv(d_in[5],  Whhb,  3 * Hh * Hh);
    conv(d_in[8],  Woutb, Vv * Hh);
    conv(d_in[10], Wembb, Ee * Vv);
    init_e_kernel<<<(Bb * Ee + 255) / 256, 256>>>(eb, sos);

    GemmArgs Z = {};

    // h0 = x @ W_agent^T + b_agent : M=4096, N=512, K=512
    {
        GemmArgs a = {xb, Wab, b_agent, h, hb, DIN, Hh};
        tcb_gemm<64, 128, 32, 32><<<dim3(Hh / 128, Bb / 64, 1), 256, SMEM_HALF>>>(
            a, Z, DIN, DIN);
    }

    for (int l = 0; l < Ll; l++) {
        // z=0: gh = h @ W_hh^T + b_hh (K=512); z=1: gi = e @ W_ih^T + b_ih (K=256)
        GemmArgs agh = {hb, Whhb, b_hh, nullptr, ghb, Hh, 3 * Hh};
        GemmArgs agi = {eb, Wihb, b_ih, nullptr, gib, Ee, 3 * Hh};
        tcb_gemm<128, 128, 64, 32><<<dim3(3 * Hh / 128, Bb / 128, 2), 256, SMEM_BIG>>>(
            agh, agi, Hh, Ee);
        // gates
        gru_gates_kernel<<<(Bb * Hh / 2 + 255) / 256, 256>>>(gib, ghb, h, hb);
        // logits = h @ W_out^T + b_out : N=512, K=512
        GemmArgs alo = {hb, Woutb, b_out, logits, nullptr, Hh, Vv};
        tcb_gemm<64, 128, 32, 32><<<dim3(Vv / 128, Bb / 64, 1), 256, SMEM_HALF>>>(
            alo, Z, Hh, Hh);
        // sample + entropy
        gumbel_softmax_kernel<<<Bb / 8, 256>>>(logits,
                                               noise + (size_t)l * Bb * Vv,
                                               seq + (size_t)l * Vv, sampb,
                                               ent + l);
        // e = sample @ W_emb^T + b_emb : N=256, K=512
        GemmArgs aem = {sampb, Wembb, b_emb, nullptr, eb, Vv, Ee};
        tcb_gemm<64, 128, 32, 32><<<dim3(Ee / 128, Bb / 64, 1), 256, SMEM_HALF>>>(
            aem, Z, Vv, Vv);
    }
    (void)in_sizes; (void)n_in; (void)out_size;
}